// round 16
// baseline (speedup 1.0000x reference)
#include <cuda_runtime.h>
#include <math.h>

#define DD 1024
#define LMAX 288
#define NBLK 296
#define LN_EPS 1e-5f
#define GELU_C 0.7978845608028654f

// ---------------- arena ----------------
constexpr size_t OFF_K  = 0;
constexpr size_t OFF_V  = OFF_K + 16ull*LMAX*DD;
constexpr size_t OFF_E  = OFF_V + 16ull*LMAX*DD;
constexpr size_t OFF_Q  = OFF_E   + 16384;   // [16][1024] row-major
constexpr size_t OFF_ATT= OFF_Q   + 16384;   // [1024][16]
constexpr size_t OFF_X1 = OFF_ATT + 16384;
constexpr size_t OFF_FC = OFF_X1  + 16384;   // [4096][16]
constexpr size_t OFF_X2 = OFF_FC  + 65536;
constexpr size_t OFF_P  = OFF_X2  + 16384;   // [16][288]
constexpr size_t OFF_C1Q= OFF_P   + 4608;
constexpr size_t OFF_DQ = OFF_C1Q + 3072;
constexpr size_t OFF_C1F= OFF_DQ  + 3072;
constexpr size_t OFF_DF = OFF_C1F + 4096;
constexpr size_t OFF_C1S= OFF_DF  + 4096;
constexpr size_t OFF_DS = OFF_C1S + 512;
constexpr size_t OFF_PMU= OFF_DS  + 512;
constexpr size_t OFF_PRS= OFF_PMU + 4096;
constexpr size_t OFF_PS1= OFF_PRS + 4096;    // [16][128]
constexpr size_t OFF_PQ1= OFF_PS1 + 2048;
constexpr size_t OFF_PS2= OFF_PQ1 + 2048;
constexpr size_t OFF_PQ2= OFF_PS2 + 2048;
constexpr size_t ARENA  = OFF_PQ2 + 2048;

__device__ float G[ARENA];
__device__ int      g_is64;
__device__ int      g_cnt16[16];
__device__ unsigned g_cnt;
__device__ unsigned g_gen;

// ---------------- grid barrier ----------------
__device__ __forceinline__ void gsync(unsigned &gen){
    __syncthreads();
    if (threadIdx.x == 0){
        __threadfence();
        if (atomicAdd(&g_cnt, 1u) == gridDim.x - 1u){
            g_cnt = 0u;
            __threadfence();
            *(volatile unsigned*)&g_gen = gen + 1u;
        } else {
            while (*(volatile unsigned*)&g_gen - gen == 0u) __nanosleep(32);
        }
        __threadfence();
    }
    __syncthreads();
    gen++;
}

// ---------------- helpers ----------------
__device__ __forceinline__ float warp_sum(float v){
    #pragma unroll
    for (int o = 16; o; o >>= 1) v += __shfl_down_sync(0xffffffffu, v, o);
    return v;
}
__device__ __forceinline__ float warp_max(float v){
    #pragma unroll
    for (int o = 16; o; o >>= 1) v = fmaxf(v, __shfl_down_sync(0xffffffffu, v, o));
    return v;
}
__device__ __forceinline__ float blk_sum256(float v, float* red){
    int lane = threadIdx.x & 31, w = threadIdx.x >> 5;
    v = warp_sum(v);
    if (lane == 0) red[w] = v;
    __syncthreads();
    if (threadIdx.x < 32){
        float x = (threadIdx.x < 8) ? red[threadIdx.x] : 0.f;
        x = warp_sum(x);
        if (threadIdx.x == 0) red[0] = x;
    }
    __syncthreads();
    float r = red[0];
    __syncthreads();
    return r;
}
__device__ __forceinline__ float blk_max256(float v, float* red){
    int lane = threadIdx.x & 31, w = threadIdx.x >> 5;
    v = warp_max(v);
    if (lane == 0) red[w] = v;
    __syncthreads();
    if (threadIdx.x < 32){
        float x = (threadIdx.x < 8) ? red[threadIdx.x] : -3.4e38f;
        x = warp_max(x);
        if (threadIdx.x == 0) red[0] = x;
    }
    __syncthreads();
    float r = red[0];
    __syncthreads();
    return r;
}
__device__ __forceinline__ float gelu_new_f(float x){
    float u = x + 0.044715f * x * x * x;
    return 0.5f * x * (1.0f + tanhf(GELU_C * u));
}
__device__ __forceinline__ void fma32(float wx, float wy, const float* Xk,
                                      float* a0, float* a1){
    const float4* xr = (const float4*)Xk;
    #pragma unroll
    for (int i = 0; i < 4; i++){
        float4 x = xr[i];
        a0[4*i+0]=fmaf(wx,x.x,a0[4*i+0]); a1[4*i+0]=fmaf(wy,x.x,a1[4*i+0]);
        a0[4*i+1]=fmaf(wx,x.y,a0[4*i+1]); a1[4*i+1]=fmaf(wy,x.y,a1[4*i+1]);
        a0[4*i+2]=fmaf(wx,x.z,a0[4*i+2]); a1[4*i+2]=fmaf(wy,x.z,a1[4*i+2]);
        a0[4*i+3]=fmaf(wx,x.w,a0[4*i+3]); a1[4*i+3]=fmaf(wy,x.w,a1[4*i+3]);
    }
}

// batched-16 GEMV, 2 n-columns per thread. Partials in sh[<=8192].
template<int NC2, bool WT, bool GAM>
__device__ void gemv2(const float* X, const float* __restrict__ W, int ldw,
                      int K, int kb, int n0, const float* __restrict__ gam, float* sh){
    constexpr int TPC = 256 / NC2;
    const int c2 = threadIdx.x & (NC2-1);
    const int sl = threadIdx.x / NC2;
    const int kper = (K - kb) / TPC;
    const int k0 = kb + sl * kper;
    const int n  = n0 + c2*2;
    float a0[16], a1[16];
    #pragma unroll
    for (int b = 0; b < 16; b++){ a0[b] = 0.f; a1[b] = 0.f; }
    if (!WT){
        #pragma unroll 2
        for (int k = k0; k < k0 + kper; k++){
            float2 w = *(const float2*)&W[(size_t)k*ldw + n];
            if (GAM){ float gk = gam[k]; w.x *= gk; w.y *= gk; }
            fma32(w.x, w.y, X + (size_t)k*16, a0, a1);
        }
    } else {
        for (int k = k0; k < k0 + kper; k += 4){
            float4 wa = *(const float4*)&W[(size_t)n*ldw + k];
            float4 wb = *(const float4*)&W[(size_t)(n+1)*ldw + k];
            if (GAM){
                float4 g4 = *(const float4*)&gam[k];
                wa.x*=g4.x; wb.x*=g4.x; wa.y*=g4.y; wb.y*=g4.y;
                wa.z*=g4.z; wb.z*=g4.z; wa.w*=g4.w; wb.w*=g4.w;
            }
            fma32(wa.x, wb.x, X + (size_t)(k+0)*16, a0, a1);
            fma32(wa.y, wb.y, X + (size_t)(k+1)*16, a0, a1);
            fma32(wa.z, wb.z, X + (size_t)(k+2)*16, a0, a1);
            fma32(wa.w, wb.w, X + (size_t)(k+3)*16, a0, a1);
        }
    }
    __syncthreads();
    float* dst = &sh[(size_t)(c2*TPC + sl)*32];
    #pragma unroll
    for (int b = 0; b < 16; b += 4){
        *(float4*)&dst[b]      = make_float4(a0[b],a0[b+1],a0[b+2],a0[b+3]);
        *(float4*)&dst[16 + b] = make_float4(a1[b],a1[b+1],a1[b+2],a1[b+3]);
    }
    __syncthreads();
}
template<int NC2>
__device__ __forceinline__ float gv2_red(const float* sh, int o){
    constexpr int TPC = 256 / NC2;
    int b = o & 15, cc = o >> 4;
    int c2 = cc >> 1, h = cc & 1;
    float r = 0.f;
    #pragma unroll 4
    for (int j = 0; j < TPC; j++) r += sh[(c2*TPC + j)*32 + h*16 + b];
    return r;
}

// stats from per-block partials ps/pq [16][128]
__device__ __forceinline__ void stats_parts128(size_t pso, size_t pqo,
                                               float* MU, float* RS, float* sh){
    int b = threadIdx.x & 15, ch = threadIdx.x >> 4;   // ch 0..15
    float s = 0.f, q = 0.f;
    #pragma unroll
    for (int i = 0; i < 8; i++){
        s += G[pso + (size_t)b*128 + ch*8 + i];
        q += G[pqo + (size_t)b*128 + ch*8 + i];
    }
    sh[threadIdx.x] = s; sh[256 + threadIdx.x] = q;
    __syncthreads();
    if (threadIdx.x < 16){
        float S = 0.f, Q = 0.f;
        #pragma unroll
        for (int g = 0; g < 16; g++){ S += sh[g*16 + threadIdx.x]; Q += sh[256 + g*16 + threadIdx.x]; }
        float mu = S * (1.f/1024.f);
        MU[threadIdx.x] = mu;
        RS[threadIdx.x] = rsqrtf(Q*(1.f/1024.f) - mu*mu + LN_EPS);
    }
    __syncthreads();
}

// ---------------- prep kernels ----------------
__device__ __forceinline__ float tokf(const int* __restrict__ t, size_t i){
    return g_is64 ? (float)t[i << 1] : (float)t[i];
}
__global__ void k_detect(const int* __restrict__ tok){
    __shared__ int cnt;
    if (threadIdx.x == 0) cnt = 0;
    __syncthreads();
    int c = 0;
    for (int i = threadIdx.x; i < 8192; i += 256)
        if (tok[2*i + 1] != 0) c++;
    atomicAdd(&cnt, c);
    __syncthreads();
    if (threadIdx.x == 0) g_is64 = (cnt == 0) ? 1 : 0;
}

__global__ void k_rowstats(const int* __restrict__ tok){
    __shared__ float red[8];
    int l = blockIdx.x, b = blockIdx.y, tid = threadIdx.x;
    size_t base = ((size_t)b*256 + l)*DD;
    float s = 0.f;
    #pragma unroll
    for (int r = 0; r < 4; r++) s += tokf(tok, base + tid + 256*r);
    s = blk_sum256(s, red);
    if (tid == 0){
        float mu = s * (1.f/1024.f);
        G[OFF_PMU + (size_t)b*255 + l] = mu;
        G[OFF_PRS + (size_t)b*255 + l] = rsqrtf(fmaxf(mu - mu*mu, 0.f) + LN_EPS);
    }
}

__global__ void k_set_e0(const int* __restrict__ tok){
    __shared__ float red[8];
    int b = blockIdx.x, tid = threadIdx.x;
    size_t base = ((size_t)b*256 + 255)*DD;
    float s = 0.f;
    #pragma unroll
    for (int r = 0; r < 4; r++){
        int d = tid + 256*r;
        float v = tokf(tok, base + d);
        G[OFF_E + (size_t)d*16 + b] = v;
        s += v;
    }
    s = blk_sum256(s, red);
    if (tid == 0) g_cnt16[b] = (int)(s + 0.5f);
}

__global__ void k_fold(const float* __restrict__ W, const float* __restrict__ gam,
                       const float* __restrict__ bet, const float* __restrict__ bias,
                       size_t c1off, size_t ddoff, int K, int N){
    __shared__ float a1[256], a2[256];
    int n = blockIdx.x*64 + (threadIdx.x & 63);
    int seg = threadIdx.x >> 6;
    float s1 = 0.f, s2 = 0.f;
    for (int k = seg; k < K; k += 4){
        float w = W[(size_t)k*N + n];
        s1 = fmaf(gam[k], w, s1);
        s2 = fmaf(bet[k], w, s2);
    }
    a1[threadIdx.x] = s1; a2[threadIdx.x] = s2;
    __syncthreads();
    if (seg == 0){
        int i = threadIdx.x;
        G[c1off + n] = a1[i] + a1[i+64] + a1[i+128] + a1[i+192];
        G[ddoff + n] = a2[i] + a2[i+64] + a2[i+128] + a2[i+192] + (bias ? bias[n] : 0.f);
    }
}
__global__ void k_folds(const float* __restrict__ W, const float* __restrict__ gam,
                        const float* __restrict__ bet, size_t c1off, size_t ddoff){
    __shared__ float red[8];
    int n = blockIdx.x;
    float s1 = 0.f, s2 = 0.f;
    for (int k = threadIdx.x; k < 1024; k += 256){
        float w = W[(size_t)n*1024 + k];
        s1 = fmaf(gam[k], w, s1);
        s2 = fmaf(bet[k], w, s2);
    }
    s1 = blk_sum256(s1, red);
    s2 = blk_sum256(s2, red);
    if (threadIdx.x == 0){ G[c1off + n] = s1; G[ddoff + n] = s2; }
}

// ---------------- prefill GEMM (binary A, gamma on B, LN fold in epilogue) ----------------
__global__ void __launch_bounds__(256) k_pre_gemm(const int* __restrict__ tok,
                                                  const float* __restrict__ Wq,
                                                  const float* __restrict__ g1){
    __shared__ float As[16][128];
    __shared__ float Bs[16][128];
    const int M = 4080;
    int tid = threadIdx.x;
    int n0 = blockIdx.x*128, m0 = blockIdx.y*128;
    int tx = tid & 15, ty = tid >> 4;
    float acc[8][8];
    #pragma unroll
    for (int i = 0; i < 8; i++)
        #pragma unroll
        for (int j = 0; j < 8; j++) acc[i][j] = 0.f;
    int ar = tid >> 2, ak = (tid & 3)*4;
    int bk = tid >> 4, bn = (tid & 15)*4;
    const int is64 = g_is64;
    size_t abase[2]; bool aok[2];
    #pragma unroll
    for (int rr = 0; rr < 2; rr++){
        int m = m0 + ar + rr*64;
        aok[rr] = (m < M);
        int bidx = m / 255, l = m - bidx*255;
        abase[rr] = ((size_t)bidx*256 + l)*1024;
    }
    for (int k0 = 0; k0 < 1024; k0 += 16){
        float gk = g1[k0 + bk];
        #pragma unroll
        for (int rr = 0; rr < 2; rr++){
            float4 a = make_float4(0.f,0.f,0.f,0.f);
            if (aok[rr]){
                size_t ix = abase[rr] + k0 + ak;
                if (is64){
                    a.x = (float)tok[(ix+0)<<1]; a.y = (float)tok[(ix+1)<<1];
                    a.z = (float)tok[(ix+2)<<1]; a.w = (float)tok[(ix+3)<<1];
                } else {
                    a.x = (float)tok[ix+0]; a.y = (float)tok[ix+1];
                    a.z = (float)tok[ix+2]; a.w = (float)tok[ix+3];
                }
            }
            As[ak+0][ar+rr*64]=a.x; As[ak+1][ar+rr*64]=a.y;
            As[ak+2][ar+rr*64]=a.z; As[ak+3][ar+rr*64]=a.w;
            float4 bv = *(const float4*)&Wq[(size_t)(k0+bk)*3072 + 1024 + n0 + bn + rr*64];
            bv.x *= gk; bv.y *= gk; bv.z *= gk; bv.w *= gk;
            *(float4*)&Bs[bk][bn+rr*64] = bv;
        }
        __syncthreads();
        #pragma unroll
        for (int kk = 0; kk < 16; kk++){
            float ra[8], rb[8];
            *(float4*)&ra[0]=*(float4*)&As[kk][ty*8]; *(float4*)&ra[4]=*(float4*)&As[kk][ty*8+4];
            *(float4*)&rb[0]=*(float4*)&Bs[kk][tx*8]; *(float4*)&rb[4]=*(float4*)&Bs[kk][tx*8+4];
            #pragma unroll
            for (int i = 0; i < 8; i++)
                #pragma unroll
                for (int j = 0; j < 8; j++) acc[i][j] = fmaf(ra[i], rb[j], acc[i][j]);
        }
        __syncthreads();
    }
    int nb = n0 + tx*8;
    float4 c1a = *(const float4*)&G[OFF_C1Q + 1024 + nb];
    float4 c1b = *(const float4*)&G[OFF_C1Q + 1024 + nb + 4];
    float4 dda = *(const float4*)&G[OFF_DQ  + 1024 + nb];
    float4 ddb = *(const float4*)&G[OFF_DQ  + 1024 + nb + 4];
    #pragma unroll
    for (int i = 0; i < 8; i++){
        int m = m0 + ty*8 + i;
        if (m >= M) continue;
        float mu = G[OFF_PMU + m], rs = G[OFF_PRS + m];
        int bidx = m/255, l = m - bidx*255;
        size_t co = ((size_t)bidx*LMAX + l)*DD;
        float4 v;
        v.x = rs*(acc[i][0] - mu*c1a.x) + dda.x;
        v.y = rs*(acc[i][1] - mu*c1a.y) + dda.y;
        v.z = rs*(acc[i][2] - mu*c1a.z) + dda.z;
        v.w = rs*(acc[i][3] - mu*c1a.w) + dda.w;
        if (nb < 1024) *(float4*)&G[OFF_K + co + nb]        = v;
        else           *(float4*)&G[OFF_V + co + nb - 1024] = v;
        v.x = rs*(acc[i][4] - mu*c1b.x) + ddb.x;
        v.y = rs*(acc[i][5] - mu*c1b.y) + ddb.y;
        v.z = rs*(acc[i][6] - mu*c1b.z) + ddb.z;
        v.w = rs*(acc[i][7] - mu*c1b.w) + ddb.w;
        if (nb + 4 < 1024) *(float4*)&G[OFF_K + co + nb + 4]        = v;
        else               *(float4*)&G[OFF_V + co + nb + 4 - 1024] = v;
    }
}

// ---------------- persistent decode kernel ----------------
__global__ void __launch_bounds__(256, 2)
k_decode(const float* __restrict__ Wqkv, const float* __restrict__ g1,
         const float* __restrict__ Wap,  const float* __restrict__ bap,
         const float* __restrict__ g2,   const float* __restrict__ Wfc,
         const float* __restrict__ Wmp,  const float* __restrict__ bmp,
         const float* __restrict__ gf,   const float* __restrict__ Wsc,
         float* __restrict__ out){
    __shared__ float sh[8192];
    __shared__ float MU[16], RS[16], red[8];
    unsigned gen = *(volatile unsigned*)&g_gen;
    const int bid = blockIdx.x, tid = threadIdx.x;

    for (int t = 0; t < 32; t++){
        const int pos = 255 + t, L = 256 + t;
        const int kb = (t == 0) ? 0 : 512;

        // ---- 1) qkv (LN1-folded, binary-E stats from counts): 192 blocks x 16n ----
        if (bid < 192){
            if (tid < 16){
                float mu = (float)g_cnt16[tid] * (1.f/1024.f);
                MU[tid] = mu;
                RS[tid] = rsqrtf(fmaxf(mu - mu*mu, 0.f) + LN_EPS);
            }
            gemv2<8,false,true>(&G[OFF_E], Wqkv, 3072, 1024, kb, bid*16, g1, sh);
            float r = gv2_red<8>(sh, tid);
            int b = tid & 15, nn = bid*16 + (tid >> 4);
            float v = RS[b]*(r - MU[b]*G[OFF_C1Q + nn]) + G[OFF_DQ + nn];
            if (nn < 1024)      G[OFF_Q + (size_t)b*1024 + nn] = v;
            else if (nn < 2048) G[OFF_K + ((size_t)b*LMAX + pos)*DD + nn - 1024] = v;
            else                G[OFF_V + ((size_t)b*LMAX + pos)*DD + nn - 2048] = v;
        }
        gsync(gen);

        if (bid == NBLK-1 && tid < 16) g_cnt16[tid] = 0;

        // ---- 2) scores: 256 blocks = 16 parts per batch ----
        if (bid < 256){
            const int b = bid >> 4, part = bid & 15;
            const int warp = tid >> 5, lane = tid & 31;
            for (int d = tid; d < 1024; d += 256) sh[d] = G[OFF_Q + (size_t)b*1024 + d];
            __syncthreads();
            float4 q[8];
            #pragma unroll
            for (int i = 0; i < 8; i++) q[i] = *(const float4*)&sh[lane*4 + i*128];
            for (int l = part + 16*warp; l < L; l += 128){
                const float4* kc = (const float4*)&G[OFF_K + ((size_t)b*LMAX + l)*DD];
                float a = 0.f;
                #pragma unroll
                for (int i = 0; i < 8; i++){
                    float4 kv = kc[lane + i*32];
                    a = fmaf(kv.x,q[i].x,a); a = fmaf(kv.y,q[i].y,a);
                    a = fmaf(kv.z,q[i].z,a); a = fmaf(kv.w,q[i].w,a);
                }
                a = warp_sum(a);
                if (lane == 0) G[OFF_P + (size_t)b*LMAX + l] = a * 0.03125f;
            }
        }
        gsync(gen);

        // ---- 3) softmax (redundant x16) + P@V: 256 blocks, 64 d each ----
        if (bid < 256){
            const int b = bid >> 4, part = bid & 15;
            for (int l = tid; l < L; l += 256) sh[l] = G[OFF_P + (size_t)b*LMAX + l];
            __syncthreads();
            float m = -3.4e38f;
            for (int l = tid; l < L; l += 256) m = fmaxf(m, sh[l]);
            m = blk_max256(m, red);
            float e = 0.f;
            for (int l = tid; l < L; l += 256){
                float ev = expf(sh[l] - m);
                sh[l] = ev; e += ev;
            }
            float iz = 1.f / blk_sum256(e, red);
            const int q4 = tid >> 6, dl = tid & 63, d = part*64 + dl;
            const float* vc = &G[OFF_V + (size_t)b*LMAX*DD + d];
            float a = 0.f;
            for (int l = q4; l < L; l += 4)
                a = fmaf(sh[l], vc[(size_t)l*DD], a);
            sh[1024 + tid] = a;
            __syncthreads();
            if (tid < 64){
                float r = (sh[1024+tid] + sh[1088+tid]) + (sh[1152+tid] + sh[1216+tid]);
                G[OFF_ATT + (size_t)(part*64 + tid)*16 + b] = r * iz;
            }
        }
        gsync(gen);

        // ---- 4) x1 = E + ATT@Wap + bap : 128 blocks x 8n (+ stats partials) ----
        if (bid < 128){
            gemv2<4,false,false>(&G[OFF_ATT], Wap, 1024, 1024, 0, bid*8, g1, sh);
            float v = 0.f;
            if (tid < 128){
                float r = gv2_red<4>(sh, tid);
                int b = tid & 15, nn = bid*8 + (tid >> 4);
                v = G[OFF_E + (size_t)nn*16 + b] + r + bap[nn];
                G[OFF_X1 + (size_t)nn*16 + b] = v;
            }
            __syncthreads();
            if (tid < 128){ sh[tid] = v; sh[128 + tid] = v*v; }
            __syncthreads();
            if (tid < 16){
                float s = 0.f, q = 0.f;
                #pragma unroll
                for (int g = 0; g < 8; g++){ s += sh[g*16 + tid]; q += sh[128 + g*16 + tid]; }
                G[OFF_PS1 + (size_t)tid*128 + bid] = s;
                G[OFF_PQ1 + (size_t)tid*128 + bid] = q;
            }
        }
        gsync(gen);

        // ---- 5) fc (LN2-folded, gelu): 128 blocks x 32n ----
        if (bid < 128){
            stats_parts128(OFF_PS1, OFF_PQ1, MU, RS, sh);
            gemv2<16,false,true>(&G[OFF_X1], Wfc, 4096, 1024, 0, bid*32, g2, sh);
            #pragma unroll
            for (int o = tid; o < 512; o += 256){
                float r = gv2_red<16>(sh, o);
                int b = o & 15, nn = bid*32 + (o >> 4);
                float v = RS[b]*(r - MU[b]*G[OFF_C1F + nn]) + G[OFF_DF + nn];
                G[OFF_FC + (size_t)nn*16 + b] = gelu_new_f(v);
            }
        }
        gsync(gen);

        // ---- 6) x2 = x1 + FC@Wmp + bmp : 128 blocks x 8n (+ stats partials) ----
        if (bid < 128){
            gemv2<4,false,false>(&G[OFF_FC], Wmp, 1024, 4096, 0, bid*8, g1, sh);
            float v = 0.f;
            if (tid < 128){
                float r = gv2_red<4>(sh, tid);
                int b = tid & 15, nn = bid*8 + (tid >> 4);
                v = G[OFF_X1 + (size_t)nn*16 + b] + r + bmp[nn];
                G[OFF_X2 + (size_t)nn*16 + b] = v;
            }
            __syncthreads();
            if (tid < 128){ sh[tid] = v; sh[128 + tid] = v*v; }
            __syncthreads();
            if (tid < 16){
                float s = 0.f, q = 0.f;
                #pragma unroll
                for (int g = 0; g < 8; g++){ s += sh[g*16 + tid]; q += sh[128 + g*16 + tid]; }
                G[OFF_PS2 + (size_t)tid*128 + bid] = s;
                G[OFF_PQ2 + (size_t)tid*128 + bid] = q;
            }
        }
        gsync(gen);

        // ---- 7) score head (LNf-folded): 64 blocks x 8n -> logits + next E + counts ----
        if (bid < 64){
            stats_parts128(OFF_PS2, OFF_PQ2, MU, RS, sh);
            gemv2<4,true,true>(&G[OFF_X2], Wsc, 1024, 1024, 0, bid*8, gf, sh);
            float one = 0.f;
            if (tid < 128){
                float r = gv2_red<4>(sh, tid);
                int b = tid & 15, nn = bid*8 + (tid >> 4);
                float lg = RS[b]*(r - MU[b]*G[OFF_C1S + nn]) + G[OFF_DS + nn];
                out[(size_t)b*16384 + (size_t)t*512 + nn] = lg;
                one = (lg > 0.f) ? 1.f : 0.f;
                G[OFF_E + (size_t)(512 + nn)*16 + b] = one;
                G[OFF_E + (size_t)nn*16 + b] = 0.f;
            }
            __syncthreads();
            if (tid < 128) sh[tid] = one;
            __syncthreads();
            if (tid < 16){
                float c = 0.f;
                #pragma unroll
                for (int g = 0; g < 8; g++) c += sh[g*16 + tid];
                atomicAdd(&g_cnt16[tid], (int)(c + 0.5f));
            }
        }
        gsync(gen);
    }
}

// ---------------- host ----------------
extern "C" void kernel_launch(void* const* d_in, const int* in_sizes, int n_in,
                              void* d_out, int out_size){
    const int*   tok     = (const int*)  d_in[0];
    const float* W_qkv   = (const float*)d_in[1];
    const float* b_qkv   = (const float*)d_in[2];
    const float* W_aproj = (const float*)d_in[3];
    const float* b_aproj = (const float*)d_in[4];
    const float* g_ln1   = (const float*)d_in[5];
    const float* b_ln1   = (const float*)d_in[6];
    const float* g_ln2   = (const float*)d_in[7];
    const float* b_ln2   = (const float*)d_in[8];
    const float* W_fc    = (const float*)d_in[9];
    const float* b_fc    = (const float*)d_in[10];
    const float* W_mproj = (const float*)d_in[11];
    const float* b_mproj = (const float*)d_in[12];
    const float* g_lnf   = (const float*)d_in[13];
    const float* b_lnf   = (const float*)d_in[14];
    const float* W_score = (const float*)d_in[15];
    float* out = (float*)d_out;

    k_detect<<<1, 256>>>(tok);
    k_fold<<<48, 256>>>(W_qkv, g_ln1, b_ln1, b_qkv, OFF_C1Q, OFF_DQ, 1024, 3072);
    k_fold<<<64, 256>>>(W_fc,  g_ln2, b_ln2, b_fc,  OFF_C1F, OFF_DF, 1024, 4096);
    k_folds<<<512, 256>>>(W_score, g_lnf, b_lnf, OFF_C1S, OFF_DS);
    k_rowstats<<<dim3(255, 16), 256>>>(tok);
    k_set_e0<<<16, 256>>>(tok);
    k_pre_gemm<<<dim3(16, 32), 256>>>(tok, W_qkv, g_ln1);
    k_decode<<<NBLK, 256>>>(W_qkv, g_ln1, W_aproj, b_aproj, g_ln2, W_fc,
                            W_mproj, b_mproj, g_lnf, W_score, out);
}

// round 17
// speedup vs baseline: 1.0748x; 1.0748x over previous
#include <cuda_runtime.h>
#include <math.h>

#define DD 1024
#define LMAX 288
#define NBLK 296
#define LN_EPS 1e-5f
#define GELU_C 0.7978845608028654f

// ---------------- arena ----------------
constexpr size_t OFF_K  = 0;
constexpr size_t OFF_V  = OFF_K + 16ull*LMAX*DD;
constexpr size_t OFF_E  = OFF_V + 16ull*LMAX*DD;
constexpr size_t OFF_Q  = OFF_E   + 16384;   // [16][1024] row-major
constexpr size_t OFF_ATT= OFF_Q   + 16384;   // [1024][16]
constexpr size_t OFF_X1 = OFF_ATT + 16384;
constexpr size_t OFF_FC = OFF_X1  + 16384;   // [4096][16]
constexpr size_t OFF_X2 = OFF_FC  + 65536;
constexpr size_t OFF_P  = OFF_X2  + 16384;   // [16][288]
constexpr size_t OFF_C1Q= OFF_P   + 4608;
constexpr size_t OFF_DQ = OFF_C1Q + 3072;
constexpr size_t OFF_C1F= OFF_DQ  + 3072;
constexpr size_t OFF_DF = OFF_C1F + 4096;
constexpr size_t OFF_C1S= OFF_DF  + 4096;
constexpr size_t OFF_DS = OFF_C1S + 512;
constexpr size_t OFF_PMU= OFF_DS  + 512;
constexpr size_t OFF_PRS= OFF_PMU + 4096;
constexpr size_t OFF_PS1= OFF_PRS + 4096;    // [16][256]
constexpr size_t OFF_PQ1= OFF_PS1 + 4096;
constexpr size_t OFF_PS2= OFF_PQ1 + 4096;
constexpr size_t OFF_PQ2= OFF_PS2 + 4096;
constexpr size_t ARENA  = OFF_PQ2 + 4096;

__device__ float G[ARENA];
__device__ int      g_is64;
__device__ int      g_cnt16[16];
__device__ unsigned g_cnt;
__device__ unsigned g_gen;

// ---------------- grid barrier ----------------
__device__ __forceinline__ void gsync(unsigned &gen){
    __syncthreads();
    if (threadIdx.x == 0){
        __threadfence();
        if (atomicAdd(&g_cnt, 1u) == gridDim.x - 1u){
            g_cnt = 0u;
            __threadfence();
            *(volatile unsigned*)&g_gen = gen + 1u;
        } else {
            while (*(volatile unsigned*)&g_gen - gen == 0u) __nanosleep(32);
        }
        __threadfence();
    }
    __syncthreads();
    gen++;
}

// ---------------- helpers ----------------
__device__ __forceinline__ float warp_sum(float v){
    #pragma unroll
    for (int o = 16; o; o >>= 1) v += __shfl_down_sync(0xffffffffu, v, o);
    return v;
}
__device__ __forceinline__ float warp_max(float v){
    #pragma unroll
    for (int o = 16; o; o >>= 1) v = fmaxf(v, __shfl_down_sync(0xffffffffu, v, o));
    return v;
}
__device__ __forceinline__ float blk_sum256(float v, float* red){
    int lane = threadIdx.x & 31, w = threadIdx.x >> 5;
    v = warp_sum(v);
    if (lane == 0) red[w] = v;
    __syncthreads();
    if (threadIdx.x < 32){
        float x = (threadIdx.x < 8) ? red[threadIdx.x] : 0.f;
        x = warp_sum(x);
        if (threadIdx.x == 0) red[0] = x;
    }
    __syncthreads();
    float r = red[0];
    __syncthreads();
    return r;
}
__device__ __forceinline__ float blk_max256(float v, float* red){
    int lane = threadIdx.x & 31, w = threadIdx.x >> 5;
    v = warp_max(v);
    if (lane == 0) red[w] = v;
    __syncthreads();
    if (threadIdx.x < 32){
        float x = (threadIdx.x < 8) ? red[threadIdx.x] : -3.4e38f;
        x = warp_max(x);
        if (threadIdx.x == 0) red[0] = x;
    }
    __syncthreads();
    float r = red[0];
    __syncthreads();
    return r;
}
__device__ __forceinline__ float gelu_new_f(float x){
    float u = x + 0.044715f * x * x * x;
    return 0.5f * x * (1.0f + tanhf(GELU_C * u));
}
__device__ __forceinline__ void fma32(float wx, float wy, const float* Xk,
                                      float* a0, float* a1){
    const float4* xr = (const float4*)Xk;
    #pragma unroll
    for (int i = 0; i < 4; i++){
        float4 x = xr[i];
        a0[4*i+0]=fmaf(wx,x.x,a0[4*i+0]); a1[4*i+0]=fmaf(wy,x.x,a1[4*i+0]);
        a0[4*i+1]=fmaf(wx,x.y,a0[4*i+1]); a1[4*i+1]=fmaf(wy,x.y,a1[4*i+1]);
        a0[4*i+2]=fmaf(wx,x.z,a0[4*i+2]); a1[4*i+2]=fmaf(wy,x.z,a1[4*i+2]);
        a0[4*i+3]=fmaf(wx,x.w,a0[4*i+3]); a1[4*i+3]=fmaf(wy,x.w,a1[4*i+3]);
    }
}

// batched-16 GEMV, 2 n-columns per thread. Partials in sh.
template<int NC2, bool WT, bool GAM>
__device__ void gemv2(const float* X, const float* __restrict__ W, int ldw,
                      int K, int kb, int n0, const float* __restrict__ gam, float* sh){
    constexpr int TPC = 256 / NC2;
    const int c2 = threadIdx.x & (NC2-1);
    const int sl = threadIdx.x / NC2;
    const int kper = (K - kb) / TPC;
    const int k0 = kb + sl * kper;
    const int n  = n0 + c2*2;
    float a0[16], a1[16];
    #pragma unroll
    for (int b = 0; b < 16; b++){ a0[b] = 0.f; a1[b] = 0.f; }
    if (!WT){
        #pragma unroll 2
        for (int k = k0; k < k0 + kper; k++){
            float2 w = *(const float2*)&W[(size_t)k*ldw + n];
            if (GAM){ float gk = gam[k]; w.x *= gk; w.y *= gk; }
            fma32(w.x, w.y, X + (size_t)k*16, a0, a1);
        }
    } else {
        for (int k = k0; k < k0 + kper; k += 4){
            float4 wa = *(const float4*)&W[(size_t)n*ldw + k];
            float4 wb = *(const float4*)&W[(size_t)(n+1)*ldw + k];
            if (GAM){
                float4 g4 = *(const float4*)&gam[k];
                wa.x*=g4.x; wb.x*=g4.x; wa.y*=g4.y; wb.y*=g4.y;
                wa.z*=g4.z; wb.z*=g4.z; wa.w*=g4.w; wb.w*=g4.w;
            }
            fma32(wa.x, wb.x, X + (size_t)(k+0)*16, a0, a1);
            fma32(wa.y, wb.y, X + (size_t)(k+1)*16, a0, a1);
            fma32(wa.z, wb.z, X + (size_t)(k+2)*16, a0, a1);
            fma32(wa.w, wb.w, X + (size_t)(k+3)*16, a0, a1);
        }
    }
    __syncthreads();
    float* dst = &sh[(size_t)(c2*TPC + sl)*32];
    #pragma unroll
    for (int b = 0; b < 16; b += 4){
        *(float4*)&dst[b]      = make_float4(a0[b],a0[b+1],a0[b+2],a0[b+3]);
        *(float4*)&dst[16 + b] = make_float4(a1[b],a1[b+1],a1[b+2],a1[b+3]);
    }
    __syncthreads();
}
template<int NC2>
__device__ __forceinline__ float gv2_red(const float* sh, int o){
    constexpr int TPC = 256 / NC2;
    int b = o & 15, cc = o >> 4;
    int c2 = cc >> 1, h = cc & 1;
    float r = 0.f;
    #pragma unroll 4
    for (int j = 0; j < TPC; j++) r += sh[(c2*TPC + j)*32 + h*16 + b];
    return r;
}

// stats from per-block partials ps/pq [16][256]
__device__ __forceinline__ void stats_parts(size_t pso, size_t pqo,
                                            float* MU, float* RS, float* sh){
    int b = threadIdx.x & 15, ch = threadIdx.x >> 4;
    float s = 0.f, q = 0.f;
    #pragma unroll
    for (int i = 0; i < 16; i++){
        s += G[pso + (size_t)b*256 + ch*16 + i];
        q += G[pqo + (size_t)b*256 + ch*16 + i];
    }
    sh[threadIdx.x] = s; sh[256 + threadIdx.x] = q;
    __syncthreads();
    if (threadIdx.x < 16){
        float S = 0.f, Q = 0.f;
        #pragma unroll
        for (int g = 0; g < 16; g++){ S += sh[g*16 + threadIdx.x]; Q += sh[256 + g*16 + threadIdx.x]; }
        float mu = S * (1.f/1024.f);
        MU[threadIdx.x] = mu;
        RS[threadIdx.x] = rsqrtf(Q*(1.f/1024.f) - mu*mu + LN_EPS);
    }
    __syncthreads();
}

// ---------------- prep kernels ----------------
__device__ __forceinline__ float tokf(const int* __restrict__ t, size_t i){
    return g_is64 ? (float)t[i << 1] : (float)t[i];
}
__global__ void k_detect(const int* __restrict__ tok){
    __shared__ int cnt;
    if (threadIdx.x == 0) cnt = 0;
    __syncthreads();
    int c = 0;
    for (int i = threadIdx.x; i < 8192; i += 256)
        if (tok[2*i + 1] != 0) c++;
    atomicAdd(&cnt, c);
    __syncthreads();
    if (threadIdx.x == 0) g_is64 = (cnt == 0) ? 1 : 0;
}

// merged fold: blocks 0..47 -> W_qkv (N=3072), blocks 48..111 -> W_fc (N=4096)
__global__ void k_foldall(const float* __restrict__ Wq, const float* __restrict__ g1,
                          const float* __restrict__ b1, const float* __restrict__ bq,
                          const float* __restrict__ Wf, const float* __restrict__ g2,
                          const float* __restrict__ b2, const float* __restrict__ bf){
    __shared__ float a1[256], a2[256];
    const float *W, *gam, *bet, *bias;
    size_t c1off, ddoff; int N, nb;
    if (blockIdx.x < 48){ W=Wq; gam=g1; bet=b1; bias=bq; c1off=OFF_C1Q; ddoff=OFF_DQ; N=3072; nb=blockIdx.x; }
    else                { W=Wf; gam=g2; bet=b2; bias=bf; c1off=OFF_C1F; ddoff=OFF_DF; N=4096; nb=blockIdx.x-48; }
    int n = nb*64 + (threadIdx.x & 63);
    int seg = threadIdx.x >> 6;
    float s1 = 0.f, s2 = 0.f;
    for (int k = seg; k < 1024; k += 4){
        float w = W[(size_t)k*N + n];
        s1 = fmaf(gam[k], w, s1);
        s2 = fmaf(bet[k], w, s2);
    }
    a1[threadIdx.x] = s1; a2[threadIdx.x] = s2;
    __syncthreads();
    if (seg == 0){
        int i = threadIdx.x;
        G[c1off + n] = a1[i] + a1[i+64] + a1[i+128] + a1[i+192];
        G[ddoff + n] = a2[i] + a2[i+64] + a2[i+128] + a2[i+192] + bias[n];
    }
}
__global__ void k_folds(const float* __restrict__ W, const float* __restrict__ gam,
                        const float* __restrict__ bet){
    __shared__ float red[8];
    int n = blockIdx.x;
    float s1 = 0.f, s2 = 0.f;
    for (int k = threadIdx.x; k < 1024; k += 256){
        float w = W[(size_t)n*1024 + k];
        s1 = fmaf(gam[k], w, s1);
        s2 = fmaf(bet[k], w, s2);
    }
    s1 = blk_sum256(s1, red);
    s2 = blk_sum256(s2, red);
    if (threadIdx.x == 0){ G[OFF_C1S + n] = s1; G[OFF_DS + n] = s2; }
}

// merged: rows 0..254 -> prefill LN stats; row 255 -> E init + counts
__global__ void k_rowstats_e0(const int* __restrict__ tok){
    __shared__ float red[8];
    int l = blockIdx.x, b = blockIdx.y, tid = threadIdx.x;
    size_t base = ((size_t)b*256 + l)*DD;
    if (l < 255){
        float s = 0.f;
        #pragma unroll
        for (int r = 0; r < 4; r++) s += tokf(tok, base + tid + 256*r);
        s = blk_sum256(s, red);
        if (tid == 0){
            float mu = s * (1.f/1024.f);
            G[OFF_PMU + (size_t)b*255 + l] = mu;
            G[OFF_PRS + (size_t)b*255 + l] = rsqrtf(fmaxf(mu - mu*mu, 0.f) + LN_EPS);
        }
    } else {
        float s = 0.f;
        #pragma unroll
        for (int r = 0; r < 4; r++){
            int d = tid + 256*r;
            float v = tokf(tok, base + d);
            G[OFF_E + (size_t)d*16 + b] = v;
            s += v;
        }
        s = blk_sum256(s, red);
        if (tid == 0) g_cnt16[b] = (int)(s + 0.5f);
    }
}

// ---------------- prefill GEMM (binary A, gamma on B, LN fold in epilogue) ----------------
__global__ void __launch_bounds__(256) k_pre_gemm(const int* __restrict__ tok,
                                                  const float* __restrict__ Wq,
                                                  const float* __restrict__ g1){
    __shared__ float As[16][128];
    __shared__ float Bs[16][128];
    const int M = 4080;
    int tid = threadIdx.x;
    int n0 = blockIdx.x*128, m0 = blockIdx.y*128;
    int tx = tid & 15, ty = tid >> 4;
    float acc[8][8];
    #pragma unroll
    for (int i = 0; i < 8; i++)
        #pragma unroll
        for (int j = 0; j < 8; j++) acc[i][j] = 0.f;
    int ar = tid >> 2, ak = (tid & 3)*4;
    int bk = tid >> 4, bn = (tid & 15)*4;
    const int is64 = g_is64;
    const int2* tok2 = (const int2*)tok;
    size_t abase[2]; bool aok[2];
    #pragma unroll
    for (int rr = 0; rr < 2; rr++){
        int m = m0 + ar + rr*64;
        aok[rr] = (m < M);
        int bidx = m / 255, l = m - bidx*255;
        abase[rr] = ((size_t)bidx*256 + l)*1024;
    }
    for (int k0 = 0; k0 < 1024; k0 += 16){
        float gk = g1[k0 + bk];
        #pragma unroll
        for (int rr = 0; rr < 2; rr++){
            float4 a = make_float4(0.f,0.f,0.f,0.f);
            if (aok[rr]){
                size_t ix = abase[rr] + k0 + ak;
                if (is64){
                    a.x = (float)tok2[ix+0].x; a.y = (float)tok2[ix+1].x;
                    a.z = (float)tok2[ix+2].x; a.w = (float)tok2[ix+3].x;
                } else {
                    int4 ti = *(const int4*)&tok[ix];
                    a.x = (float)ti.x; a.y = (float)ti.y;
                    a.z = (float)ti.z; a.w = (float)ti.w;
                }
            }
            As[ak+0][ar+rr*64]=a.x; As[ak+1][ar+rr*64]=a.y;
            As[ak+2][ar+rr*64]=a.z; As[ak+3][ar+rr*64]=a.w;
            float4 bv = *(const float4*)&Wq[(size_t)(k0+bk)*3072 + 1024 + n0 + bn + rr*64];
            bv.x *= gk; bv.y *= gk; bv.z *= gk; bv.w *= gk;
            *(float4*)&Bs[bk][bn+rr*64] = bv;
        }
        __syncthreads();
        #pragma unroll
        for (int kk = 0; kk < 16; kk++){
            float ra[8], rb[8];
            *(float4*)&ra[0]=*(float4*)&As[kk][ty*8]; *(float4*)&ra[4]=*(float4*)&As[kk][ty*8+4];
            *(float4*)&rb[0]=*(float4*)&Bs[kk][tx*8]; *(float4*)&rb[4]=*(float4*)&Bs[kk][tx*8+4];
            #pragma unroll
            for (int i = 0; i < 8; i++)
                #pragma unroll
                for (int j = 0; j < 8; j++) acc[i][j] = fmaf(ra[i], rb[j], acc[i][j]);
        }
        __syncthreads();
    }
    int nb = n0 + tx*8;
    float4 c1a = *(const float4*)&G[OFF_C1Q + 1024 + nb];
    float4 c1b = *(const float4*)&G[OFF_C1Q + 1024 + nb + 4];
    float4 dda = *(const float4*)&G[OFF_DQ  + 1024 + nb];
    float4 ddb = *(const float4*)&G[OFF_DQ  + 1024 + nb + 4];
    #pragma unroll
    for (int i = 0; i < 8; i++){
        int m = m0 + ty*8 + i;
        if (m >= M) continue;
        float mu = G[OFF_PMU + m], rs = G[OFF_PRS + m];
        int bidx = m/255, l = m - bidx*255;
        size_t co = ((size_t)bidx*LMAX + l)*DD;
        float4 v;
        v.x = rs*(acc[i][0] - mu*c1a.x) + dda.x;
        v.y = rs*(acc[i][1] - mu*c1a.y) + dda.y;
        v.z = rs*(acc[i][2] - mu*c1a.z) + dda.z;
        v.w = rs*(acc[i][3] - mu*c1a.w) + dda.w;
        if (nb < 1024) *(float4*)&G[OFF_K + co + nb]        = v;
        else           *(float4*)&G[OFF_V + co + nb - 1024] = v;
        v.x = rs*(acc[i][4] - mu*c1b.x) + ddb.x;
        v.y = rs*(acc[i][5] - mu*c1b.y) + ddb.y;
        v.z = rs*(acc[i][6] - mu*c1b.z) + ddb.z;
        v.w = rs*(acc[i][7] - mu*c1b.w) + ddb.w;
        if (nb + 4 < 1024) *(float4*)&G[OFF_K + co + nb + 4]        = v;
        else               *(float4*)&G[OFF_V + co + nb + 4 - 1024] = v;
    }
}

// ---------------- persistent decode kernel ----------------
__global__ void __launch_bounds__(256, 2)
k_decode(const float* __restrict__ Wqkv, const float* __restrict__ g1,
         const float* __restrict__ Wap,  const float* __restrict__ bap,
         const float* __restrict__ g2,   const float* __restrict__ Wfc,
         const float* __restrict__ Wmp,  const float* __restrict__ bmp,
         const float* __restrict__ gf,   const float* __restrict__ Wsc,
         float* __restrict__ out){
    __shared__ float sh[8192];
    __shared__ float MU[16], RS[16], red[8];
    unsigned gen = *(volatile unsigned*)&g_gen;
    const int bid = blockIdx.x, tid = threadIdx.x;

    for (int t = 0; t < 32; t++){
        const int pos = 255 + t, L = 256 + t;
        const int kb = (t == 0) ? 0 : 512;

        // ---- 1) qkv (LN1-folded, binary-E stats from counts): 192 blocks x 16n ----
        if (bid < 192){
            if (tid < 16){
                float mu = (float)g_cnt16[tid] * (1.f/1024.f);
                MU[tid] = mu;
                RS[tid] = rsqrtf(fmaxf(mu - mu*mu, 0.f) + LN_EPS);
            }
            gemv2<8,false,true>(&G[OFF_E], Wqkv, 3072, 1024, kb, bid*16, g1, sh);
            float r = gv2_red<8>(sh, tid);
            int b = tid & 15, nn = bid*16 + (tid >> 4);
            float v = RS[b]*(r - MU[b]*G[OFF_C1Q + nn]) + G[OFF_DQ + nn];
            if (nn < 1024)      G[OFF_Q + (size_t)b*1024 + nn] = v;
            else if (nn < 2048) G[OFF_K + ((size_t)b*LMAX + pos)*DD + nn - 1024] = v;
            else                G[OFF_V + ((size_t)b*LMAX + pos)*DD + nn - 2048] = v;
        }
        gsync(gen);

        if (bid == NBLK-1 && tid < 16) g_cnt16[tid] = 0;

        // ---- 2) scores: 256 blocks = 16 parts per batch ----
        if (bid < 256){
            const int b = bid >> 4, part = bid & 15;
            const int warp = tid >> 5, lane = tid & 31;
            for (int d = tid; d < 1024; d += 256) sh[d] = G[OFF_Q + (size_t)b*1024 + d];
            __syncthreads();
            float4 q[8];
            #pragma unroll
            for (int i = 0; i < 8; i++) q[i] = *(const float4*)&sh[lane*4 + i*128];
            for (int l = part + 16*warp; l < L; l += 128){
                const float4* kc = (const float4*)&G[OFF_K + ((size_t)b*LMAX + l)*DD];
                float a = 0.f;
                #pragma unroll
                for (int i = 0; i < 8; i++){
                    float4 kv = kc[lane + i*32];
                    a = fmaf(kv.x,q[i].x,a); a = fmaf(kv.y,q[i].y,a);
                    a = fmaf(kv.z,q[i].z,a); a = fmaf(kv.w,q[i].w,a);
                }
                a = warp_sum(a);
                if (lane == 0) G[OFF_P + (size_t)b*LMAX + l] = a * 0.03125f;
            }
        }
        gsync(gen);

        // ---- 3) softmax (redundant x16) + P@V: 256 blocks, 64 d each ----
        if (bid < 256){
            const int b = bid >> 4, part = bid & 15;
            for (int l = tid; l < L; l += 256) sh[l] = G[OFF_P + (size_t)b*LMAX + l];
            __syncthreads();
            float m = -3.4e38f;
            for (int l = tid; l < L; l += 256) m = fmaxf(m, sh[l]);
            m = blk_max256(m, red);
            float e = 0.f;
            for (int l = tid; l < L; l += 256){
                float ev = expf(sh[l] - m);
                sh[l] = ev; e += ev;
            }
            float iz = 1.f / blk_sum256(e, red);
            const int q4 = tid >> 6, dl = tid & 63, d = part*64 + dl;
            const float* vc = &G[OFF_V + (size_t)b*LMAX*DD + d];
            float a = 0.f;
            for (int l = q4; l < L; l += 4)
                a = fmaf(sh[l], vc[(size_t)l*DD], a);
            sh[1024 + tid] = a;
            __syncthreads();
            if (tid < 64){
                float r = (sh[1024+tid] + sh[1088+tid]) + (sh[1152+tid] + sh[1216+tid]);
                G[OFF_ATT + (size_t)(part*64 + tid)*16 + b] = r * iz;
            }
        }
        gsync(gen);

        // ---- 4) x1 = E + ATT@Wap + bap : 256 blocks x 4n (+ stats partials) ----
        if (bid < 256){
            gemv2<2,false,false>(&G[OFF_ATT], Wap, 1024, 1024, 0, bid*4, g1, sh);
            float v = 0.f;
            if (tid < 64){
                float r = gv2_red<2>(sh, tid);
                int b = tid & 15, nn = bid*4 + (tid >> 4);
                v = G[OFF_E + (size_t)nn*16 + b] + r + bap[nn];
                G[OFF_X1 + (size_t)nn*16 + b] = v;
            }
            __syncthreads();
            if (tid < 64){ sh[tid] = v; sh[64 + tid] = v*v; }
            __syncthreads();
            if (tid < 16){
                float s = sh[tid] + sh[16+tid] + sh[32+tid] + sh[48+tid];
                float q = sh[64+tid] + sh[80+tid] + sh[96+tid] + sh[112+tid];
                G[OFF_PS1 + (size_t)tid*256 + bid] = s;
                G[OFF_PQ1 + (size_t)tid*256 + bid] = q;
            }
        }
        gsync(gen);

        // ---- 5) fc (LN2-folded, gelu): 256 blocks x 16n ----
        if (bid < 256){
            stats_parts(OFF_PS1, OFF_PQ1, MU, RS, sh);
            gemv2<8,false,true>(&G[OFF_X1], Wfc, 4096, 1024, 0, bid*16, g2, sh);
            float r = gv2_red<8>(sh, tid);
            int b = tid & 15, nn = bid*16 + (tid >> 4);
            float v = RS[b]*(r - MU[b]*G[OFF_C1F + nn]) + G[OFF_DF + nn];
            G[OFF_FC + (size_t)nn*16 + b] = gelu_new_f(v);
        }
        gsync(gen);

        // ---- 6) x2 = x1 + FC@Wmp + bmp : 256 blocks x 4n (+ stats partials) ----
        if (bid < 256){
            gemv2<2,false,false>(&G[OFF_FC], Wmp, 1024, 4096, 0, bid*4, g1, sh);
            float v = 0.f;
            if (tid < 64){
                float r = gv2_red<2>(sh, tid);
                int b = tid & 15, nn = bid*4 + (tid >> 4);
                v = G[OFF_X1 + (size_t)nn*16 + b] + r + bmp[nn];
                G[OFF_X2 + (size_t)nn*16 + b] = v;
            }
            __syncthreads();
            if (tid < 64){ sh[tid] = v; sh[64 + tid] = v*v; }
            __syncthreads();
            if (tid < 16){
                float s = sh[tid] + sh[16+tid] + sh[32+tid] + sh[48+tid];
                float q = sh[64+tid] + sh[80+tid] + sh[96+tid] + sh[112+tid];
                G[OFF_PS2 + (size_t)tid*256 + bid] = s;
                G[OFF_PQ2 + (size_t)tid*256 + bid] = q;
            }
        }
        gsync(gen);

        // ---- 7) score head (LNf-folded): 128 blocks x 4n -> logits + next E + counts ----
        if (bid < 128){
            stats_parts(OFF_PS2, OFF_PQ2, MU, RS, sh);
            gemv2<2,true,true>(&G[OFF_X2], Wsc, 1024, 1024, 0, bid*4, gf, sh);
            float one = 0.f;
            if (tid < 64){
                float r = gv2_red<2>(sh, tid);
                int b = tid & 15, nn = bid*4 + (tid >> 4);
                float lg = RS[b]*(r - MU[b]*G[OFF_C1S + nn]) + G[OFF_DS + nn];
                out[(size_t)b*16384 + (size_t)t*512 + nn] = lg;
                one = (lg > 0.f) ? 1.f : 0.f;
                G[OFF_E + (size_t)(512 + nn)*16 + b] = one;
                G[OFF_E + (size_t)nn*16 + b] = 0.f;
            }
            __syncthreads();
            if (tid < 64) sh[tid] = one;
            __syncthreads();
            if (tid < 16){
                float c = sh[tid] + sh[16+tid] + sh[32+tid] + sh[48+tid];
                atomicAdd(&g_cnt16[tid], (int)(c + 0.5f));
            }
        }
        gsync(gen);
    }
}

// ---------------- host ----------------
extern "C" void kernel_launch(void* const* d_in, const int* in_sizes, int n_in,
                              void* d_out, int out_size){
    const int*   tok     = (const int*)  d_in[0];
    const float* W_qkv   = (const float*)d_in[1];
    const float* b_qkv   = (const float*)d_in[2];
    const float* W_aproj = (const float*)d_in[3];
    const float* b_aproj = (const float*)d_in[4];
    const float* g_ln1   = (const float*)d_in[5];
    const float* b_ln1   = (const float*)d_in[6];
    const float* g_ln2   = (const float*)d_in[7];
    const float* b_ln2   = (const float*)d_in[8];
    const float* W_fc    = (const float*)d_in[9];
    const float* b_fc    = (const float*)d_in[10];
    const float* W_mproj = (const float*)d_in[11];
    const float* b_mproj = (const float*)d_in[12];
    const float* g_lnf   = (const float*)d_in[13];
    const float* b_lnf   = (const float*)d_in[14];
    const float* W_score = (const float*)d_in[15];
    float* out = (float*)d_out;

    // exactly 5 launches before k_decode so ncu (-s 5 -c 1) captures the decode kernel
    k_detect<<<1, 256>>>(tok);                                            // 0
    k_foldall<<<112, 256>>>(W_qkv, g_ln1, b_ln1, b_qkv,
                            W_fc,  g_ln2, b_ln2, b_fc);                   // 1
    k_folds<<<512, 256>>>(W_score, g_lnf, b_lnf);                         // 2
    k_rowstats_e0<<<dim3(256, 16), 256>>>(tok);                           // 3
    k_pre_gemm<<<dim3(16, 32), 256>>>(tok, W_qkv, g_ln1);                 // 4
    k_decode<<<NBLK, 256>>>(W_qkv, g_ln1, W_aproj, b_aproj, g_ln2, W_fc,  // 5
                            W_mproj, b_mproj, g_lnf, W_score, out);
}